// round 5
// baseline (speedup 1.0000x reference)
#include <cuda_runtime.h>
#include <cuda_bf16.h>
#include <math.h>

// Problem constants
#define NNODES 200000
#define NEDGES 600000
#define NGRAPHS 4000
#define IN_DIM 25
#define EDGE_DIM 11
#define HID 128
#define DEPTH 4
#define KMSG (HID + EDGE_DIM)   // 139
#define KUP  (2 * HID)          // 256
#define BN_EPS 1e-5f

// Packed fp32x2 FMA (sm_100+): d.lo += a.lo*b.lo, d.hi += a.hi*b.hi
#define FMA2(acc, a, b) \
    asm("fma.rn.f32x2 %0, %1, %2, %0;" : "+l"(acc) : "l"(a), "l"(b))
#define UNPACK2(lo, hi, p) \
    asm("mov.b64 {%0, %1}, %2;" : "=f"(lo), "=f"(hi) : "l"(p))

// Vector atomic add (sm_90+): one 16B reduction instead of 4 scalar REDs
__device__ __forceinline__ void red_add_v4(float* p, float4 v)
{
    asm volatile("red.global.add.v4.f32 [%0], {%1, %2, %3, %4};"
                 :: "l"(p), "f"(v.x), "f"(v.y), "f"(v.z), "f"(v.w)
                 : "memory");
}

// Scratch (static device globals)
__device__ float g_hbuf[2][(size_t)NNODES * HID];  // ping-pong node features (PRE-norm)
__device__ float g_aggr[(size_t)NNODES * HID];     // scatter-add target
__device__ float g_bnsum[HID];
__device__ float g_bnsq[HID];
__device__ float g_scale[HID];                     // BN affine of previous layer
__device__ float g_shift[HID];
__device__ float g_cnt[NGRAPHS];

extern __shared__ float sm_dyn[];

// ---------------------------------------------------------------------------
// Init: zero aggr, BN stats, counts, output; scale=1, shift=0
// ---------------------------------------------------------------------------
__global__ void init_kernel(float* __restrict__ out)
{
    size_t idx = (size_t)blockIdx.x * blockDim.x + threadIdx.x;
    size_t stride = (size_t)gridDim.x * blockDim.x;
    float4 z4 = {0.f, 0.f, 0.f, 0.f};
    float4* a4 = (float4*)g_aggr;
    for (size_t i = idx; i < (size_t)NNODES * HID / 4; i += stride) a4[i] = z4;
    for (size_t i = idx; i < (size_t)NGRAPHS * HID; i += stride) out[i] = 0.f;
    for (size_t i = idx; i < NGRAPHS; i += stride) g_cnt[i] = 0.f;
    if (blockIdx.x == 0 && threadIdx.x < HID) {
        g_bnsum[threadIdx.x] = 0.f;
        g_bnsq[threadIdx.x] = 0.f;
        g_scale[threadIdx.x] = 1.f;
        g_shift[threadIdx.x] = 0.f;
    }
}

// ---------------------------------------------------------------------------
// Input projection: h0 = lrelu(x @ W_in + b_in)
// ---------------------------------------------------------------------------
__global__ __launch_bounds__(128) void input_proj_kernel(
    const float* __restrict__ x, const float* __restrict__ W,
    const float* __restrict__ b)
{
    __shared__ float xs[8][IN_DIM];
    const int n0 = blockIdx.x * 8;
    const int c = threadIdx.x;

    for (int i = threadIdx.x; i < 8 * IN_DIM; i += 128) {
        int r = i / IN_DIM, k = i - r * IN_DIM;
        xs[r][k] = x[(size_t)(n0 + r) * IN_DIM + k];
    }
    __syncthreads();

    float wcol[IN_DIM];
#pragma unroll
    for (int k = 0; k < IN_DIM; k++) wcol[k] = W[k * HID + c];
    const float bias = b[c];

#pragma unroll
    for (int r = 0; r < 8; r++) {
        float acc = bias;
#pragma unroll
        for (int k = 0; k < IN_DIM; k++) acc = fmaf(xs[r][k], wcol[k], acc);
        g_hbuf[0][(size_t)(n0 + r) * HID + c] = acc > 0.f ? acc : 0.1f * acc;
    }
}

// ---------------------------------------------------------------------------
// Edge message + scatter-add, f32x2 packed over k-pairs.
// Weights TRANSPOSED in smem: Ws_t[c][k], k-stride KPAD=140.
// 64 edges/block, 256 thr (8 warps x 8 edges), 105KB smem -> 2 CTAs/SM.
// Epilogue: warp-local transpose through own ins rows, then red.v4 (8 vector
// atomics per thread instead of 32 scalar).
// ---------------------------------------------------------------------------
#define ETILE 64
#define KPAD 140                 // 35 float4 chunks (k 0..138 data, 139 zero)
#define KPAD4 (KPAD / 4)         // 35
#define EDGE_SMEM ((HID * KPAD + ETILE * KPAD) * 4)  // 107520

__global__ __launch_bounds__(256, 2) void edge_msg_kernel(
    int sel, const int* __restrict__ src, const int* __restrict__ dst,
    const float* __restrict__ eattr,
    const float* __restrict__ Wm, const float* __restrict__ bm)
{
    float* Ws = sm_dyn;                  // transposed [128 c][140 k]
    float* ins = sm_dyn + HID * KPAD;    // [64 e][140 k]
    const float* __restrict__ h_in = g_hbuf[sel];

    const int tid = threadIdx.x;
    const int lane = tid & 31;
    const int wid = tid >> 5;
    const int eb = blockIdx.x * ETILE;

    // Stage W_msg TRANSPOSED: Ws[c*KPAD + k] = Wm[k*HID + c]; zero k=139.
    {
        float4* Ws4 = (float4*)Ws;
        for (int i = tid; i < KPAD4 * HID; i += 256) {
            const int c = i & 127;
            const int k4 = i >> 7;
            float4 v;
            v.x = (4 * k4 + 0 < KMSG) ? Wm[(4 * k4 + 0) * HID + c] : 0.f;
            v.y = (4 * k4 + 1 < KMSG) ? Wm[(4 * k4 + 1) * HID + c] : 0.f;
            v.z = (4 * k4 + 2 < KMSG) ? Wm[(4 * k4 + 2) * HID + c] : 0.f;
            v.w = (4 * k4 + 3 < KMSG) ? Wm[(4 * k4 + 3) * HID + c] : 0.f;
            Ws4[c * KPAD4 + k4] = v;
        }
    }
    // Gather h[src] rows with BN affine applied (k 0..127)
    {
        const float4 sc4 = ((const float4*)g_scale)[lane];
        const float4 of4 = ((const float4*)g_shift)[lane];
        for (int e = wid; e < ETILE; e += 8) {
            int s = src[eb + e];
            float4 v = *(const float4*)(h_in + (size_t)s * HID + lane * 4);
            v.x = fmaf(v.x, sc4.x, of4.x);
            v.y = fmaf(v.y, sc4.y, of4.y);
            v.z = fmaf(v.z, sc4.z, of4.z);
            v.w = fmaf(v.w, sc4.w, of4.w);
            *(float4*)(ins + e * KPAD + lane * 4) = v;
        }
    }
    // edge_attr (k 128..138) + zero pad (k 139)
    for (int i = tid; i < ETILE * (EDGE_DIM + 1); i += 256) {
        int e = i / (EDGE_DIM + 1), k = i - e * (EDGE_DIM + 1);
        ins[e * KPAD + HID + k] =
            (k < EDGE_DIM) ? eattr[(size_t)(eb + e) * EDGE_DIM + k] : 0.f;
    }
    __syncthreads();

    const int e0 = wid * 8;
    unsigned long long acc[8][4];
#pragma unroll
    for (int e = 0; e < 8; e++)
#pragma unroll
        for (int j = 0; j < 4; j++) acc[e][j] = 0ULL;

    const ulonglong2* Wst2 = (const ulonglong2*)Ws;
    const ulonglong2* ins2 = (const ulonglong2*)(ins + e0 * KPAD);

    for (int k4 = 0; k4 < KPAD4; k4++) {
        const ulonglong2 w0 = Wst2[(lane) * KPAD4 + k4];
        const ulonglong2 w1 = Wst2[(lane + 32) * KPAD4 + k4];
        const ulonglong2 w2 = Wst2[(lane + 64) * KPAD4 + k4];
        const ulonglong2 w3 = Wst2[(lane + 96) * KPAD4 + k4];
#pragma unroll
        for (int e = 0; e < 8; e++) {
            const ulonglong2 v = ins2[e * KPAD4 + k4];   // broadcast
            FMA2(acc[e][0], v.x, w0.x); FMA2(acc[e][0], v.y, w0.y);
            FMA2(acc[e][1], v.x, w1.x); FMA2(acc[e][1], v.y, w1.y);
            FMA2(acc[e][2], v.x, w2.x); FMA2(acc[e][2], v.y, w2.y);
            FMA2(acc[e][3], v.x, w3.x); FMA2(acc[e][3], v.y, w3.y);
        }
    }

    // Epilogue: bias + lrelu, stage into this warp's OWN ins rows (done
    // reading them; no other warp touches them), transpose, vector atomics.
    const float b0 = bm[lane], b1 = bm[lane + 32], b2 = bm[lane + 64], b3 = bm[lane + 96];
#pragma unroll
    for (int e = 0; e < 8; e++) {
        float* srow = ins + (e0 + e) * KPAD;
        float lo, hi;
        UNPACK2(lo, hi, acc[e][0]);
        float z0 = lo + hi + b0; z0 = z0 > 0.f ? z0 : 0.1f * z0;
        UNPACK2(lo, hi, acc[e][1]);
        float z1 = lo + hi + b1; z1 = z1 > 0.f ? z1 : 0.1f * z1;
        UNPACK2(lo, hi, acc[e][2]);
        float z2 = lo + hi + b2; z2 = z2 > 0.f ? z2 : 0.1f * z2;
        UNPACK2(lo, hi, acc[e][3]);
        float z3 = lo + hi + b3; z3 = z3 > 0.f ? z3 : 0.1f * z3;
        srow[lane] = z0; srow[lane + 32] = z1;
        srow[lane + 64] = z2; srow[lane + 96] = z3;
    }
    __syncwarp();
#pragma unroll
    for (int e = 0; e < 8; e++) {
        const int d = dst[eb + e0 + e];
        const float4 v = *(const float4*)(ins + (e0 + e) * KPAD + lane * 4);
        red_add_v4(g_aggr + (size_t)d * HID + lane * 4, v);
    }
}

// ---------------------------------------------------------------------------
// Update: out = relu(cat[aggr, h_affine] @ W_up + b_up) + BN stats.
// 64 rows/block, 128 cols, 8 warps x 8 rows, f32x2 over k-pairs, two K-phases.
// Phase 0 also ZEROES the aggr tile right after staging it (removes the
// separate 102MB zeroing pass for the next layer).
// ---------------------------------------------------------------------------
#define UNTILE 64
#define UKP 132
#define UKP4 (UKP / 4)           // 33
#define KHALF 128
#define KHALF4 (KHALF / 4)       // 32
#define UPD_SMEM ((HID * UKP + UNTILE * KHALF) * 4)  // 100352

__global__ __launch_bounds__(256, 2) void update_kernel(
    int sel, const float* __restrict__ Wu, const float* __restrict__ bu)
{
    float* Ws = sm_dyn;                  // transposed [128 c][132 k-pad]
    float* ins = sm_dyn + HID * UKP;     // [64 r][128 k]
    __shared__ float s_sum[HID], s_sq[HID];

    const float* __restrict__ h_in = g_hbuf[sel];
    float* __restrict__ h_out = g_hbuf[sel ^ 1];

    const int tid = threadIdx.x;
    const int lane = tid & 31;
    const int wid = tid >> 5;
    const int n0 = blockIdx.x * UNTILE;

    if (tid < HID) { s_sum[tid] = 0.f; s_sq[tid] = 0.f; }

    const int r0 = wid * 8;
    unsigned long long acc[8][4];
#pragma unroll
    for (int r = 0; r < 8; r++)
#pragma unroll
        for (int j = 0; j < 4; j++) acc[r][j] = 0ULL;

    const ulonglong2* Wst2 = (const ulonglong2*)Ws;
    const ulonglong2* ins2 = (const ulonglong2*)(ins + r0 * KHALF);

#pragma unroll 1
    for (int p = 0; p < 2; p++) {
        // Stage weight half TRANSPOSED: Ws[c*UKP + kk] = Wu[(p*128+kk)*HID + c]
        {
            float4* Ws4 = (float4*)Ws;
            for (int i = tid; i < KHALF4 * HID; i += 256) {
                const int c = i & 127;
                const int k4 = i >> 7;
                float4 v;
                v.x = Wu[(p * KHALF + 4 * k4 + 0) * HID + c];
                v.y = Wu[(p * KHALF + 4 * k4 + 1) * HID + c];
                v.z = Wu[(p * KHALF + 4 * k4 + 2) * HID + c];
                v.w = Wu[(p * KHALF + 4 * k4 + 3) * HID + c];
                Ws4[c * UKP4 + k4] = v;
            }
        }
        // Stage ins rows: phase0 = aggr (raw, then zero it), phase1 = h (affine)
        {
            float4* ins4 = (float4*)ins;
            if (p == 0) {
                const float4 z4 = {0.f, 0.f, 0.f, 0.f};
                for (int i = tid; i < UNTILE * 32; i += 256) {
                    int r = i >> 5, q = i & 31;
                    float4* ap = (float4*)(g_aggr + (size_t)(n0 + r) * HID + q * 4);
                    ins4[i] = *ap;
                    *ap = z4;        // pre-zero for next layer's scatter
                }
            } else {
                for (int i = tid; i < UNTILE * 32; i += 256) {
                    int r = i >> 5, q = i & 31;
                    float4 v = *(const float4*)(h_in + (size_t)(n0 + r) * HID + q * 4);
                    float4 sc = ((const float4*)g_scale)[q];
                    float4 of = ((const float4*)g_shift)[q];
                    v.x = fmaf(v.x, sc.x, of.x);
                    v.y = fmaf(v.y, sc.y, of.y);
                    v.z = fmaf(v.z, sc.z, of.z);
                    v.w = fmaf(v.w, sc.w, of.w);
                    ins4[i] = v;
                }
            }
        }
        __syncthreads();

        for (int k4 = 0; k4 < KHALF4; k4++) {
            const ulonglong2 w0 = Wst2[(lane) * UKP4 + k4];
            const ulonglong2 w1 = Wst2[(lane + 32) * UKP4 + k4];
            const ulonglong2 w2 = Wst2[(lane + 64) * UKP4 + k4];
            const ulonglong2 w3 = Wst2[(lane + 96) * UKP4 + k4];
#pragma unroll
            for (int r = 0; r < 8; r++) {
                const ulonglong2 v = ins2[r * KHALF4 + k4];   // broadcast
                FMA2(acc[r][0], v.x, w0.x); FMA2(acc[r][0], v.y, w0.y);
                FMA2(acc[r][1], v.x, w1.x); FMA2(acc[r][1], v.y, w1.y);
                FMA2(acc[r][2], v.x, w2.x); FMA2(acc[r][2], v.y, w2.y);
                FMA2(acc[r][3], v.x, w3.x); FMA2(acc[r][3], v.y, w3.y);
            }
        }
        __syncthreads();  // before restaging / epilogue
    }

    const float b0 = bu[lane], b1 = bu[lane + 32], b2 = bu[lane + 64], b3 = bu[lane + 96];
    float psum[4] = {0.f, 0.f, 0.f, 0.f};
    float psq[4] = {0.f, 0.f, 0.f, 0.f};
#pragma unroll
    for (int r = 0; r < 8; r++) {
        float* orow = h_out + (size_t)(n0 + r0 + r) * HID;
        float lo, hi;
        UNPACK2(lo, hi, acc[r][0]); float z0 = fmaxf(lo + hi + b0, 0.f);
        UNPACK2(lo, hi, acc[r][1]); float z1 = fmaxf(lo + hi + b1, 0.f);
        UNPACK2(lo, hi, acc[r][2]); float z2 = fmaxf(lo + hi + b2, 0.f);
        UNPACK2(lo, hi, acc[r][3]); float z3 = fmaxf(lo + hi + b3, 0.f);
        orow[lane] = z0; orow[lane + 32] = z1; orow[lane + 64] = z2; orow[lane + 96] = z3;
        psum[0] += z0; psum[1] += z1; psum[2] += z2; psum[3] += z3;
        psq[0] += z0 * z0; psq[1] += z1 * z1; psq[2] += z2 * z2; psq[3] += z3 * z3;
    }
    atomicAdd(&s_sum[lane], psum[0]);      atomicAdd(&s_sq[lane], psq[0]);
    atomicAdd(&s_sum[lane + 32], psum[1]); atomicAdd(&s_sq[lane + 32], psq[1]);
    atomicAdd(&s_sum[lane + 64], psum[2]); atomicAdd(&s_sq[lane + 64], psq[2]);
    atomicAdd(&s_sum[lane + 96], psum[3]); atomicAdd(&s_sq[lane + 96], psq[3]);
    __syncthreads();
    if (tid < HID) {
        atomicAdd(&g_bnsum[tid], s_sum[tid]);
        atomicAdd(&g_bnsq[tid], s_sq[tid]);
    }
}

// ---------------------------------------------------------------------------
// BN coefficients only (aggr zeroing fused into update_kernel)
// ---------------------------------------------------------------------------
__global__ void coef_kernel(const float* __restrict__ gamma,
                            const float* __restrict__ beta)
{
    int c = threadIdx.x;
    if (c < HID) {
        float mu = g_bnsum[c] * (1.f / NNODES);
        float var = g_bnsq[c] * (1.f / NNODES) - mu * mu;
        var = fmaxf(var, 0.f);
        float s = gamma[c] * rsqrtf(var + BN_EPS);
        g_scale[c] = s;
        g_shift[c] = beta[c] - mu * s;
        g_bnsum[c] = 0.f;
        g_bnsq[c] = 0.f;
    }
}

// ---------------------------------------------------------------------------
// Pooling: segmented (batch is sorted); applies final BN affine
// ---------------------------------------------------------------------------
#define PNODES 32
__global__ __launch_bounds__(128) void pool_kernel(
    const int* __restrict__ batch, float* __restrict__ out)
{
    const float* __restrict__ h = g_hbuf[DEPTH & 1];
    const int n0 = blockIdx.x * PNODES;
    const int c = threadIdx.x;
    const float sc = g_scale[c];
    const float of = g_shift[c];

    int gprev = batch[n0];
    float acc = 0.f;
    int cnt = 0;
#pragma unroll 4
    for (int r = 0; r < PNODES; r++) {
        const int n = n0 + r;
        const int g = batch[n];
        const float v = fmaf(h[(size_t)n * HID + c], sc, of);
        if (g != gprev) {
            atomicAdd(&out[(size_t)gprev * HID + c], acc);
            if (c == 0) atomicAdd(&g_cnt[gprev], (float)cnt);
            acc = 0.f; cnt = 0; gprev = g;
        }
        acc += v; cnt++;
    }
    atomicAdd(&out[(size_t)gprev * HID + c], acc);
    if (c == 0) atomicAdd(&g_cnt[gprev], (float)cnt);
}

__global__ void pool_div_kernel(float* __restrict__ out)
{
    size_t i = (size_t)blockIdx.x * blockDim.x + threadIdx.x;
    if (i < (size_t)NGRAPHS * HID) {
        int g = (int)(i >> 7);
        out[i] /= fmaxf(g_cnt[g], 1.f);
    }
}

// ---------------------------------------------------------------------------
// Launch
// ---------------------------------------------------------------------------
extern "C" void kernel_launch(void* const* d_in, const int* in_sizes, int n_in,
                              void* d_out, int out_size)
{
    const float* x      = (const float*)d_in[0];
    const int*   eidx   = (const int*)d_in[1];     // [2, E]
    const float* eattr  = (const float*)d_in[2];
    const int*   batch  = (const int*)d_in[3];
    const float* W_in   = (const float*)d_in[4];
    const float* b_in   = (const float*)d_in[5];
    const float* W_msg  = (const float*)d_in[6];   // [4,139,128]
    const float* b_msg  = (const float*)d_in[7];   // [4,128]
    const float* W_up   = (const float*)d_in[8];   // [4,256,128]
    const float* b_up   = (const float*)d_in[9];   // [4,128]
    const float* gamma  = (const float*)d_in[10];
    const float* beta   = (const float*)d_in[11];
    float* out = (float*)d_out;

    const int* src = eidx;
    const int* dst = eidx + NEDGES;

    cudaFuncSetAttribute(edge_msg_kernel, cudaFuncAttributeMaxDynamicSharedMemorySize, EDGE_SMEM);
    cudaFuncSetAttribute(update_kernel, cudaFuncAttributeMaxDynamicSharedMemorySize, UPD_SMEM);

    init_kernel<<<2048, 256>>>(out);
    input_proj_kernel<<<NNODES / 8, 128>>>(x, W_in, b_in);

    for (int i = 0; i < DEPTH; i++) {
        edge_msg_kernel<<<NEDGES / ETILE, 256, EDGE_SMEM>>>(
            i & 1, src, dst, eattr, W_msg + (size_t)i * KMSG * HID, b_msg + i * HID);
        update_kernel<<<NNODES / UNTILE, 256, UPD_SMEM>>>(
            i & 1, W_up + (size_t)i * KUP * HID, b_up + i * HID);
        coef_kernel<<<1, 128>>>(gamma + i * HID, beta + i * HID);
    }

    pool_kernel<<<NNODES / PNODES, 128>>>(batch, out);
    pool_div_kernel<<<(NGRAPHS * HID + 255) / 256, 256>>>(out);
}

// round 10
// speedup vs baseline: 1.3511x; 1.3511x over previous
#include <cuda_runtime.h>
#include <cuda_bf16.h>
#include <math.h>

// Problem constants
#define NNODES 200000
#define NEDGES 600000
#define NGRAPHS 4000
#define IN_DIM 25
#define EDGE_DIM 11
#define HID 128
#define DEPTH 4
#define KMSG (HID + EDGE_DIM)   // 139
#define KUP  (2 * HID)          // 256
#define BN_EPS 1e-5f

// Packed fp32x2 FMA (sm_100+): d.lo += a.lo*b.lo, d.hi += a.hi*b.hi
#define FMA2(acc, a, b) \
    asm("fma.rn.f32x2 %0, %1, %2, %0;" : "+l"(acc) : "l"(a), "l"(b))
#define UNPACK2(lo, hi, p) \
    asm("mov.b64 {%0, %1}, %2;" : "=f"(lo), "=f"(hi) : "l"(p))

// Vector atomic add (sm_90+): one 16B reduction instead of 4 scalar REDs
__device__ __forceinline__ void red_add_v4(float* p, float4 v)
{
    asm volatile("red.global.add.v4.f32 [%0], {%1, %2, %3, %4};"
                 :: "l"(p), "f"(v.x), "f"(v.y), "f"(v.z), "f"(v.w)
                 : "memory");
}

// Scratch (static device globals)
__device__ float g_hbuf[2][(size_t)NNODES * HID];  // ping-pong node features (PRE-norm)
__device__ float g_aggr[(size_t)NNODES * HID];     // scatter-add target
__device__ float g_bnsum[HID];
__device__ float g_bnsq[HID];
__device__ float g_scale[HID];                     // BN affine of previous layer
__device__ float g_shift[HID];
__device__ float g_cnt[NGRAPHS];

extern __shared__ float sm_dyn[];

// ---------------------------------------------------------------------------
// Init: zero aggr, BN stats, counts, output; scale=1, shift=0
// ---------------------------------------------------------------------------
__global__ void init_kernel(float* __restrict__ out)
{
    size_t idx = (size_t)blockIdx.x * blockDim.x + threadIdx.x;
    size_t stride = (size_t)gridDim.x * blockDim.x;
    float4 z4 = {0.f, 0.f, 0.f, 0.f};
    float4* a4 = (float4*)g_aggr;
    for (size_t i = idx; i < (size_t)NNODES * HID / 4; i += stride) a4[i] = z4;
    for (size_t i = idx; i < (size_t)NGRAPHS * HID; i += stride) out[i] = 0.f;
    for (size_t i = idx; i < NGRAPHS; i += stride) g_cnt[i] = 0.f;
    if (blockIdx.x == 0 && threadIdx.x < HID) {
        g_bnsum[threadIdx.x] = 0.f;
        g_bnsq[threadIdx.x] = 0.f;
        g_scale[threadIdx.x] = 1.f;
        g_shift[threadIdx.x] = 0.f;
    }
}

// ---------------------------------------------------------------------------
// Input projection: h0 = lrelu(x @ W_in + b_in)
// ---------------------------------------------------------------------------
__global__ __launch_bounds__(128) void input_proj_kernel(
    const float* __restrict__ x, const float* __restrict__ W,
    const float* __restrict__ b)
{
    __shared__ float xs[8][IN_DIM];
    const int n0 = blockIdx.x * 8;
    const int c = threadIdx.x;

    for (int i = threadIdx.x; i < 8 * IN_DIM; i += 128) {
        int r = i / IN_DIM, k = i - r * IN_DIM;
        xs[r][k] = x[(size_t)(n0 + r) * IN_DIM + k];
    }
    __syncthreads();

    float wcol[IN_DIM];
#pragma unroll
    for (int k = 0; k < IN_DIM; k++) wcol[k] = W[k * HID + c];
    const float bias = b[c];

#pragma unroll
    for (int r = 0; r < 8; r++) {
        float acc = bias;
#pragma unroll
        for (int k = 0; k < IN_DIM; k++) acc = fmaf(xs[r][k], wcol[k], acc);
        g_hbuf[0][(size_t)(n0 + r) * HID + c] = acc > 0.f ? acc : 0.1f * acc;
    }
}

// ---------------------------------------------------------------------------
// Edge message + scatter-add, f32x2 packed over k-pairs.
// Weights TRANSPOSED in smem: Ws_t[c][k], k-stride KPAD=140.
// 64 edges/block, 256 thr (8 warps x 8 edges), 105KB smem -> 2 CTAs/SM.
// Epilogue: warp-local transpose through own ins rows, then red.v4 (8 vector
// atomics per thread instead of 32 scalar).
// ---------------------------------------------------------------------------
#define ETILE 64
#define KPAD 140                 // 35 float4 chunks (k 0..138 data, 139 zero)
#define KPAD4 (KPAD / 4)         // 35
#define EDGE_SMEM ((HID * KPAD + ETILE * KPAD) * 4)  // 107520

__global__ __launch_bounds__(256, 2) void edge_msg_kernel(
    int sel, const int* __restrict__ src, const int* __restrict__ dst,
    const float* __restrict__ eattr,
    const float* __restrict__ Wm, const float* __restrict__ bm)
{
    float* Ws = sm_dyn;                  // transposed [128 c][140 k]
    float* ins = sm_dyn + HID * KPAD;    // [64 e][140 k]
    const float* __restrict__ h_in = g_hbuf[sel];

    const int tid = threadIdx.x;
    const int lane = tid & 31;
    const int wid = tid >> 5;
    const int eb = blockIdx.x * ETILE;

    // Stage W_msg TRANSPOSED: Ws[c*KPAD + k] = Wm[k*HID + c]; zero k=139.
    {
        float4* Ws4 = (float4*)Ws;
        for (int i = tid; i < KPAD4 * HID; i += 256) {
            const int c = i & 127;
            const int k4 = i >> 7;
            float4 v;
            v.x = (4 * k4 + 0 < KMSG) ? Wm[(4 * k4 + 0) * HID + c] : 0.f;
            v.y = (4 * k4 + 1 < KMSG) ? Wm[(4 * k4 + 1) * HID + c] : 0.f;
            v.z = (4 * k4 + 2 < KMSG) ? Wm[(4 * k4 + 2) * HID + c] : 0.f;
            v.w = (4 * k4 + 3 < KMSG) ? Wm[(4 * k4 + 3) * HID + c] : 0.f;
            Ws4[c * KPAD4 + k4] = v;
        }
    }
    // Gather h[src] rows with BN affine applied (k 0..127)
    {
        const float4 sc4 = ((const float4*)g_scale)[lane];
        const float4 of4 = ((const float4*)g_shift)[lane];
        for (int e = wid; e < ETILE; e += 8) {
            int s = src[eb + e];
            float4 v = *(const float4*)(h_in + (size_t)s * HID + lane * 4);
            v.x = fmaf(v.x, sc4.x, of4.x);
            v.y = fmaf(v.y, sc4.y, of4.y);
            v.z = fmaf(v.z, sc4.z, of4.z);
            v.w = fmaf(v.w, sc4.w, of4.w);
            *(float4*)(ins + e * KPAD + lane * 4) = v;
        }
    }
    // edge_attr (k 128..138) + zero pad (k 139)
    for (int i = tid; i < ETILE * (EDGE_DIM + 1); i += 256) {
        int e = i / (EDGE_DIM + 1), k = i - e * (EDGE_DIM + 1);
        ins[e * KPAD + HID + k] =
            (k < EDGE_DIM) ? eattr[(size_t)(eb + e) * EDGE_DIM + k] : 0.f;
    }
    __syncthreads();

    const int e0 = wid * 8;
    unsigned long long acc[8][4];
#pragma unroll
    for (int e = 0; e < 8; e++)
#pragma unroll
        for (int j = 0; j < 4; j++) acc[e][j] = 0ULL;

    const ulonglong2* Wst2 = (const ulonglong2*)Ws;
    const ulonglong2* ins2 = (const ulonglong2*)(ins + e0 * KPAD);

    for (int k4 = 0; k4 < KPAD4; k4++) {
        const ulonglong2 w0 = Wst2[(lane) * KPAD4 + k4];
        const ulonglong2 w1 = Wst2[(lane + 32) * KPAD4 + k4];
        const ulonglong2 w2 = Wst2[(lane + 64) * KPAD4 + k4];
        const ulonglong2 w3 = Wst2[(lane + 96) * KPAD4 + k4];
#pragma unroll
        for (int e = 0; e < 8; e++) {
            const ulonglong2 v = ins2[e * KPAD4 + k4];   // broadcast
            FMA2(acc[e][0], v.x, w0.x); FMA2(acc[e][0], v.y, w0.y);
            FMA2(acc[e][1], v.x, w1.x); FMA2(acc[e][1], v.y, w1.y);
            FMA2(acc[e][2], v.x, w2.x); FMA2(acc[e][2], v.y, w2.y);
            FMA2(acc[e][3], v.x, w3.x); FMA2(acc[e][3], v.y, w3.y);
        }
    }

    // Epilogue: bias + lrelu, stage into this warp's OWN ins rows (done
    // reading them; no other warp touches them), transpose, vector atomics.
    const float b0 = bm[lane], b1 = bm[lane + 32], b2 = bm[lane + 64], b3 = bm[lane + 96];
#pragma unroll
    for (int e = 0; e < 8; e++) {
        float* srow = ins + (e0 + e) * KPAD;
        float lo, hi;
        UNPACK2(lo, hi, acc[e][0]);
        float z0 = lo + hi + b0; z0 = z0 > 0.f ? z0 : 0.1f * z0;
        UNPACK2(lo, hi, acc[e][1]);
        float z1 = lo + hi + b1; z1 = z1 > 0.f ? z1 : 0.1f * z1;
        UNPACK2(lo, hi, acc[e][2]);
        float z2 = lo + hi + b2; z2 = z2 > 0.f ? z2 : 0.1f * z2;
        UNPACK2(lo, hi, acc[e][3]);
        float z3 = lo + hi + b3; z3 = z3 > 0.f ? z3 : 0.1f * z3;
        srow[lane] = z0; srow[lane + 32] = z1;
        srow[lane + 64] = z2; srow[lane + 96] = z3;
    }
    __syncwarp();
#pragma unroll
    for (int e = 0; e < 8; e++) {
        const int d = dst[eb + e0 + e];
        const float4 v = *(const float4*)(ins + (e0 + e) * KPAD + lane * 4);
        red_add_v4(g_aggr + (size_t)d * HID + lane * 4, v);
    }
}

// ---------------------------------------------------------------------------
// Update: out = relu(cat[aggr, h_affine] @ W_up + b_up) + BN stats.
// 64 rows/block, 128 cols, 8 warps x 8 rows, f32x2 over k-pairs, two K-phases.
// Phase-0 staging is PURE LOADS (the R5 fused zero-write created same-address
// load->store hazards that serialized staging at memory latency; reverted).
// ---------------------------------------------------------------------------
#define UNTILE 64
#define UKP 132
#define UKP4 (UKP / 4)           // 33
#define KHALF 128
#define KHALF4 (KHALF / 4)       // 32
#define UPD_SMEM ((HID * UKP + UNTILE * KHALF) * 4)  // 100352

__global__ __launch_bounds__(256, 2) void update_kernel(
    int sel, const float* __restrict__ Wu, const float* __restrict__ bu)
{
    float* Ws = sm_dyn;                  // transposed [128 c][132 k-pad]
    float* ins = sm_dyn + HID * UKP;     // [64 r][128 k]
    __shared__ float s_sum[HID], s_sq[HID];

    const float* __restrict__ h_in = g_hbuf[sel];
    float* __restrict__ h_out = g_hbuf[sel ^ 1];

    const int tid = threadIdx.x;
    const int lane = tid & 31;
    const int wid = tid >> 5;
    const int n0 = blockIdx.x * UNTILE;

    if (tid < HID) { s_sum[tid] = 0.f; s_sq[tid] = 0.f; }

    const int r0 = wid * 8;
    unsigned long long acc[8][4];
#pragma unroll
    for (int r = 0; r < 8; r++)
#pragma unroll
        for (int j = 0; j < 4; j++) acc[r][j] = 0ULL;

    const ulonglong2* Wst2 = (const ulonglong2*)Ws;
    const ulonglong2* ins2 = (const ulonglong2*)(ins + r0 * KHALF);

#pragma unroll 1
    for (int p = 0; p < 2; p++) {
        // Stage weight half TRANSPOSED: Ws[c*UKP + kk] = Wu[(p*128+kk)*HID + c]
        {
            float4* Ws4 = (float4*)Ws;
            for (int i = tid; i < KHALF4 * HID; i += 256) {
                const int c = i & 127;
                const int k4 = i >> 7;
                float4 v;
                v.x = Wu[(p * KHALF + 4 * k4 + 0) * HID + c];
                v.y = Wu[(p * KHALF + 4 * k4 + 1) * HID + c];
                v.z = Wu[(p * KHALF + 4 * k4 + 2) * HID + c];
                v.w = Wu[(p * KHALF + 4 * k4 + 3) * HID + c];
                Ws4[c * UKP4 + k4] = v;
            }
        }
        // Stage ins rows: phase0 = aggr (raw), phase1 = h (affine)
        {
            float4* ins4 = (float4*)ins;
            if (p == 0) {
                for (int i = tid; i < UNTILE * 32; i += 256) {
                    int r = i >> 5, q = i & 31;
                    ins4[i] = *(const float4*)(g_aggr + (size_t)(n0 + r) * HID + q * 4);
                }
            } else {
                for (int i = tid; i < UNTILE * 32; i += 256) {
                    int r = i >> 5, q = i & 31;
                    float4 v = *(const float4*)(h_in + (size_t)(n0 + r) * HID + q * 4);
                    float4 sc = ((const float4*)g_scale)[q];
                    float4 of = ((const float4*)g_shift)[q];
                    v.x = fmaf(v.x, sc.x, of.x);
                    v.y = fmaf(v.y, sc.y, of.y);
                    v.z = fmaf(v.z, sc.z, of.z);
                    v.w = fmaf(v.w, sc.w, of.w);
                    ins4[i] = v;
                }
            }
        }
        __syncthreads();

        for (int k4 = 0; k4 < KHALF4; k4++) {
            const ulonglong2 w0 = Wst2[(lane) * UKP4 + k4];
            const ulonglong2 w1 = Wst2[(lane + 32) * UKP4 + k4];
            const ulonglong2 w2 = Wst2[(lane + 64) * UKP4 + k4];
            const ulonglong2 w3 = Wst2[(lane + 96) * UKP4 + k4];
#pragma unroll
            for (int r = 0; r < 8; r++) {
                const ulonglong2 v = ins2[r * KHALF4 + k4];   // broadcast
                FMA2(acc[r][0], v.x, w0.x); FMA2(acc[r][0], v.y, w0.y);
                FMA2(acc[r][1], v.x, w1.x); FMA2(acc[r][1], v.y, w1.y);
                FMA2(acc[r][2], v.x, w2.x); FMA2(acc[r][2], v.y, w2.y);
                FMA2(acc[r][3], v.x, w3.x); FMA2(acc[r][3], v.y, w3.y);
            }
        }
        __syncthreads();  // before restaging / epilogue
    }

    const float b0 = bu[lane], b1 = bu[lane + 32], b2 = bu[lane + 64], b3 = bu[lane + 96];
    float psum[4] = {0.f, 0.f, 0.f, 0.f};
    float psq[4] = {0.f, 0.f, 0.f, 0.f};
#pragma unroll
    for (int r = 0; r < 8; r++) {
        float* orow = h_out + (size_t)(n0 + r0 + r) * HID;
        float lo, hi;
        UNPACK2(lo, hi, acc[r][0]); float z0 = fmaxf(lo + hi + b0, 0.f);
        UNPACK2(lo, hi, acc[r][1]); float z1 = fmaxf(lo + hi + b1, 0.f);
        UNPACK2(lo, hi, acc[r][2]); float z2 = fmaxf(lo + hi + b2, 0.f);
        UNPACK2(lo, hi, acc[r][3]); float z3 = fmaxf(lo + hi + b3, 0.f);
        orow[lane] = z0; orow[lane + 32] = z1; orow[lane + 64] = z2; orow[lane + 96] = z3;
        psum[0] += z0; psum[1] += z1; psum[2] += z2; psum[3] += z3;
        psq[0] += z0 * z0; psq[1] += z1 * z1; psq[2] += z2 * z2; psq[3] += z3 * z3;
    }
    atomicAdd(&s_sum[lane], psum[0]);      atomicAdd(&s_sq[lane], psq[0]);
    atomicAdd(&s_sum[lane + 32], psum[1]); atomicAdd(&s_sq[lane + 32], psq[1]);
    atomicAdd(&s_sum[lane + 64], psum[2]); atomicAdd(&s_sq[lane + 64], psq[2]);
    atomicAdd(&s_sum[lane + 96], psum[3]); atomicAdd(&s_sq[lane + 96], psq[3]);
    __syncthreads();
    if (tid < HID) {
        atomicAdd(&g_bnsum[tid], s_sum[tid]);
        atomicAdd(&g_bnsq[tid], s_sq[tid]);
    }
}

// ---------------------------------------------------------------------------
// BN coefficients + zero aggr for next layer (+ reset stats)
// Independent streaming stores only — no load/store same-address hazards.
// ---------------------------------------------------------------------------
__global__ void coef_zero_kernel(const float* __restrict__ gamma,
                                 const float* __restrict__ beta)
{
    size_t idx = (size_t)blockIdx.x * blockDim.x + threadIdx.x;
    size_t stride = (size_t)gridDim.x * blockDim.x;
    float4 z4 = {0.f, 0.f, 0.f, 0.f};
    float4* a4 = (float4*)g_aggr;
    for (size_t i = idx; i < (size_t)NNODES * HID / 4; i += stride) a4[i] = z4;
    if (blockIdx.x == 0 && threadIdx.x < HID) {
        int c = threadIdx.x;
        float mu = g_bnsum[c] * (1.f / NNODES);
        float var = g_bnsq[c] * (1.f / NNODES) - mu * mu;
        var = fmaxf(var, 0.f);
        float s = gamma[c] * rsqrtf(var + BN_EPS);
        g_scale[c] = s;
        g_shift[c] = beta[c] - mu * s;
        g_bnsum[c] = 0.f;
        g_bnsq[c] = 0.f;
    }
}

// ---------------------------------------------------------------------------
// Pooling: segmented (batch is sorted); applies final BN affine
// ---------------------------------------------------------------------------
#define PNODES 32
__global__ __launch_bounds__(128) void pool_kernel(
    const int* __restrict__ batch, float* __restrict__ out)
{
    const float* __restrict__ h = g_hbuf[DEPTH & 1];
    const int n0 = blockIdx.x * PNODES;
    const int c = threadIdx.x;
    const float sc = g_scale[c];
    const float of = g_shift[c];

    int gprev = batch[n0];
    float acc = 0.f;
    int cnt = 0;
#pragma unroll 4
    for (int r = 0; r < PNODES; r++) {
        const int n = n0 + r;
        const int g = batch[n];
        const float v = fmaf(h[(size_t)n * HID + c], sc, of);
        if (g != gprev) {
            atomicAdd(&out[(size_t)gprev * HID + c], acc);
            if (c == 0) atomicAdd(&g_cnt[gprev], (float)cnt);
            acc = 0.f; cnt = 0; gprev = g;
        }
        acc += v; cnt++;
    }
    atomicAdd(&out[(size_t)gprev * HID + c], acc);
    if (c == 0) atomicAdd(&g_cnt[gprev], (float)cnt);
}

__global__ void pool_div_kernel(float* __restrict__ out)
{
    size_t i = (size_t)blockIdx.x * blockDim.x + threadIdx.x;
    if (i < (size_t)NGRAPHS * HID) {
        int g = (int)(i >> 7);
        out[i] /= fmaxf(g_cnt[g], 1.f);
    }
}

// ---------------------------------------------------------------------------
// Launch
// ---------------------------------------------------------------------------
extern "C" void kernel_launch(void* const* d_in, const int* in_sizes, int n_in,
                              void* d_out, int out_size)
{
    const float* x      = (const float*)d_in[0];
    const int*   eidx   = (const int*)d_in[1];     // [2, E]
    const float* eattr  = (const float*)d_in[2];
    const int*   batch  = (const int*)d_in[3];
    const float* W_in   = (const float*)d_in[4];
    const float* b_in   = (const float*)d_in[5];
    const float* W_msg  = (const float*)d_in[6];   // [4,139,128]
    const float* b_msg  = (const float*)d_in[7];   // [4,128]
    const float* W_up   = (const float*)d_in[8];   // [4,256,128]
    const float* b_up   = (const float*)d_in[9];   // [4,128]
    const float* gamma  = (const float*)d_in[10];
    const float* beta   = (const float*)d_in[11];
    float* out = (float*)d_out;

    const int* src = eidx;
    const int* dst = eidx + NEDGES;

    cudaFuncSetAttribute(edge_msg_kernel, cudaFuncAttributeMaxDynamicSharedMemorySize, EDGE_SMEM);
    cudaFuncSetAttribute(update_kernel, cudaFuncAttributeMaxDynamicSharedMemorySize, UPD_SMEM);

    init_kernel<<<2048, 256>>>(out);
    input_proj_kernel<<<NNODES / 8, 128>>>(x, W_in, b_in);

    for (int i = 0; i < DEPTH; i++) {
        edge_msg_kernel<<<NEDGES / ETILE, 256, EDGE_SMEM>>>(
            i & 1, src, dst, eattr, W_msg + (size_t)i * KMSG * HID, b_msg + i * HID);
        update_kernel<<<NNODES / UNTILE, 256, UPD_SMEM>>>(
            i & 1, W_up + (size_t)i * KUP * HID, b_up + i * HID);
        coef_zero_kernel<<<2048, 256>>>(gamma + i * HID, beta + i * HID);
    }

    pool_kernel<<<NNODES / PNODES, 128>>>(batch, out);
    pool_div_kernel<<<(NGRAPHS * HID + 255) / 256, 256>>>(out);
}

// round 15
// speedup vs baseline: 1.9601x; 1.4507x over previous
#include <cuda_runtime.h>
#include <cuda_bf16.h>
#include <math.h>

// Problem constants
#define NNODES 200000
#define NEDGES 600000
#define NGRAPHS 4000
#define IN_DIM 25
#define EDGE_DIM 11
#define HID 128
#define DEPTH 4
#define KMSG (HID + EDGE_DIM)   // 139
#define KUP  (2 * HID)          // 256
#define BN_EPS 1e-5f

// Packed fp32x2 FMA (sm_100+)
#define FMA2(acc, a, b) \
    asm("fma.rn.f32x2 %0, %1, %2, %0;" : "+l"(acc) : "l"(a), "l"(b))
#define UNPACK2(lo, hi, p) \
    asm("mov.b64 {%0, %1}, %2;" : "=f"(lo), "=f"(hi) : "l"(p))

// Vector atomic add (sm_90+)
__device__ __forceinline__ void red_add_v4(float* p, float4 v)
{
    asm volatile("red.global.add.v4.f32 [%0], {%1, %2, %3, %4};"
                 :: "l"(p), "f"(v.x), "f"(v.y), "f"(v.z), "f"(v.w)
                 : "memory");
}

// Scratch (static device globals)
__device__ float g_hbuf[2][(size_t)NNODES * HID];  // ping-pong node features (PRE-norm)
__device__ float g_aggr[(size_t)NNODES * HID];     // scatter-add target
__device__ float g_msgA[(size_t)NNODES * HID];     // per-node message part h_aff @ W_h
__device__ float g_bnsum[HID];
__device__ float g_bnsq[HID];
__device__ float g_scale[HID];                     // BN affine of previous layer
__device__ float g_shift[HID];
__device__ float g_cnt[NGRAPHS];

extern __shared__ float sm_dyn[];

// ---------------------------------------------------------------------------
// Init
// ---------------------------------------------------------------------------
__global__ void init_kernel(float* __restrict__ out)
{
    size_t idx = (size_t)blockIdx.x * blockDim.x + threadIdx.x;
    size_t stride = (size_t)gridDim.x * blockDim.x;
    float4 z4 = {0.f, 0.f, 0.f, 0.f};
    float4* a4 = (float4*)g_aggr;
    for (size_t i = idx; i < (size_t)NNODES * HID / 4; i += stride) a4[i] = z4;
    for (size_t i = idx; i < (size_t)NGRAPHS * HID; i += stride) out[i] = 0.f;
    for (size_t i = idx; i < NGRAPHS; i += stride) g_cnt[i] = 0.f;
    if (blockIdx.x == 0 && threadIdx.x < HID) {
        g_bnsum[threadIdx.x] = 0.f;
        g_bnsq[threadIdx.x] = 0.f;
        g_scale[threadIdx.x] = 1.f;
        g_shift[threadIdx.x] = 0.f;
    }
}

// ---------------------------------------------------------------------------
// Input projection: h0 = lrelu(x @ W_in + b_in)
// ---------------------------------------------------------------------------
__global__ __launch_bounds__(128) void input_proj_kernel(
    const float* __restrict__ x, const float* __restrict__ W,
    const float* __restrict__ b)
{
    __shared__ float xs[8][IN_DIM];
    const int n0 = blockIdx.x * 8;
    const int c = threadIdx.x;

    for (int i = threadIdx.x; i < 8 * IN_DIM; i += 128) {
        int r = i / IN_DIM, k = i - r * IN_DIM;
        xs[r][k] = x[(size_t)(n0 + r) * IN_DIM + k];
    }
    __syncthreads();

    float wcol[IN_DIM];
#pragma unroll
    for (int k = 0; k < IN_DIM; k++) wcol[k] = W[k * HID + c];
    const float bias = b[c];

#pragma unroll
    for (int r = 0; r < 8; r++) {
        float acc = bias;
#pragma unroll
        for (int k = 0; k < IN_DIM; k++) acc = fmaf(xs[r][k], wcol[k], acc);
        g_hbuf[0][(size_t)(n0 + r) * HID + c] = acc > 0.f ? acc : 0.1f * acc;
    }
}

// ---------------------------------------------------------------------------
// Per-NODE message part: A = h_affine @ W_msg[0:128]  (no bias, no lrelu).
// Same proven shape as update_kernel, single K=128 phase.
// 64 rows/block, 8 warps x 8 rows, f32x2 over k-pairs.
// smem = 128*132*4 + 64*128*4 = 100352 -> 2 CTAs/SM.
// ---------------------------------------------------------------------------
#define MKP 132
#define MKP4 (MKP / 4)           // 33
#define MSG_SMEM ((HID * MKP + 64 * HID) * 4)  // 100352

__global__ __launch_bounds__(256, 2) void msg_node_kernel(
    int sel, const float* __restrict__ Wm)
{
    float* Ws = sm_dyn;                  // transposed [128 c][132 k-pad]
    float* ins = sm_dyn + HID * MKP;     // [64 r][128 k]
    const float* __restrict__ h_in = g_hbuf[sel];

    const int tid = threadIdx.x;
    const int lane = tid & 31;
    const int wid = tid >> 5;
    const int n0 = blockIdx.x * 64;

    // Stage W_h (rows 0..127 of Wm) TRANSPOSED
    {
        float4* Ws4 = (float4*)Ws;
        for (int i = tid; i < 32 * HID; i += 256) {
            const int c = i & 127;
            const int k4 = i >> 7;
            float4 v;
            v.x = Wm[(4 * k4 + 0) * HID + c];
            v.y = Wm[(4 * k4 + 1) * HID + c];
            v.z = Wm[(4 * k4 + 2) * HID + c];
            v.w = Wm[(4 * k4 + 3) * HID + c];
            Ws4[c * MKP4 + k4] = v;
        }
    }
    // Stage h rows with BN affine applied
    {
        float4* ins4 = (float4*)ins;
        for (int i = tid; i < 64 * 32; i += 256) {
            int r = i >> 5, q = i & 31;
            float4 v = *(const float4*)(h_in + (size_t)(n0 + r) * HID + q * 4);
            float4 sc = ((const float4*)g_scale)[q];
            float4 of = ((const float4*)g_shift)[q];
            v.x = fmaf(v.x, sc.x, of.x);
            v.y = fmaf(v.y, sc.y, of.y);
            v.z = fmaf(v.z, sc.z, of.z);
            v.w = fmaf(v.w, sc.w, of.w);
            ins4[i] = v;
        }
    }
    __syncthreads();

    const int r0 = wid * 8;
    unsigned long long acc[8][4];
#pragma unroll
    for (int r = 0; r < 8; r++)
#pragma unroll
        for (int j = 0; j < 4; j++) acc[r][j] = 0ULL;

    const ulonglong2* Wst2 = (const ulonglong2*)Ws;
    const ulonglong2* ins2 = (const ulonglong2*)(ins + r0 * HID);

    for (int k4 = 0; k4 < 32; k4++) {
        const ulonglong2 w0 = Wst2[(lane) * MKP4 + k4];
        const ulonglong2 w1 = Wst2[(lane + 32) * MKP4 + k4];
        const ulonglong2 w2 = Wst2[(lane + 64) * MKP4 + k4];
        const ulonglong2 w3 = Wst2[(lane + 96) * MKP4 + k4];
#pragma unroll
        for (int r = 0; r < 8; r++) {
            const ulonglong2 v = ins2[r * 32 + k4];   // broadcast
            FMA2(acc[r][0], v.x, w0.x); FMA2(acc[r][0], v.y, w0.y);
            FMA2(acc[r][1], v.x, w1.x); FMA2(acc[r][1], v.y, w1.y);
            FMA2(acc[r][2], v.x, w2.x); FMA2(acc[r][2], v.y, w2.y);
            FMA2(acc[r][3], v.x, w3.x); FMA2(acc[r][3], v.y, w3.y);
        }
    }

#pragma unroll
    for (int r = 0; r < 8; r++) {
        float* orow = g_msgA + (size_t)(n0 + r0 + r) * HID;
        float lo, hi;
        UNPACK2(lo, hi, acc[r][0]); orow[lane] = lo + hi;
        UNPACK2(lo, hi, acc[r][1]); orow[lane + 32] = lo + hi;
        UNPACK2(lo, hi, acc[r][2]); orow[lane + 64] = lo + hi;
        UNPACK2(lo, hi, acc[r][3]); orow[lane + 96] = lo + hi;
    }
}

// ---------------------------------------------------------------------------
// Per-EDGE: msg = lrelu(A[src] + eattr @ W_e + b); scatter to aggr[dst].
// One warp per edge: lane owns cols [4*lane, 4*lane+4). W_e (11x128) in
// registers (11 float4/lane). 240 edges/block (8 warps x 30), eattr staged
// to smem for coalescing. Gather + red.v4 are 512B contiguous per edge.
// ---------------------------------------------------------------------------
#define EB 240

__global__ __launch_bounds__(256) void edge_scatter_kernel(
    const int* __restrict__ src, const int* __restrict__ dst,
    const float* __restrict__ eattr,
    const float* __restrict__ Wm, const float* __restrict__ bm)
{
    __shared__ float se[EB * EDGE_DIM];   // 10560 B

    const int tid = threadIdx.x;
    const int lane = tid & 31;
    const int wid = tid >> 5;
    const int eb = blockIdx.x * EB;

    // Edge-part weights into registers: wreg[k] = W_msg[128+k][4*lane..+3]
    float4 wreg[EDGE_DIM];
#pragma unroll
    for (int k = 0; k < EDGE_DIM; k++)
        wreg[k] = *(const float4*)(Wm + (size_t)(HID + k) * HID + lane * 4);
    const float4 b4 = *(const float4*)(bm + lane * 4);

    // Stage eattr rows (coalesced)
    for (int i = tid; i < EB * EDGE_DIM; i += 256)
        se[i] = eattr[(size_t)eb * EDGE_DIM + i];
    __syncthreads();

    const int e0 = wid * 30;
#pragma unroll 3
    for (int i = 0; i < 30; i++) {
        const int e = e0 + i;
        const int s = src[eb + e];
        const int d = dst[eb + e];
        const float4 a = *(const float4*)(g_msgA + (size_t)s * HID + lane * 4);
        const float* ep = se + e * EDGE_DIM;

        float4 z;
        z.x = a.x + b4.x; z.y = a.y + b4.y; z.z = a.z + b4.z; z.w = a.w + b4.w;
#pragma unroll
        for (int k = 0; k < EDGE_DIM; k++) {
            const float ev = ep[k];                 // smem broadcast
            z.x = fmaf(ev, wreg[k].x, z.x);
            z.y = fmaf(ev, wreg[k].y, z.y);
            z.z = fmaf(ev, wreg[k].z, z.z);
            z.w = fmaf(ev, wreg[k].w, z.w);
        }
        z.x = z.x > 0.f ? z.x : 0.1f * z.x;
        z.y = z.y > 0.f ? z.y : 0.1f * z.y;
        z.z = z.z > 0.f ? z.z : 0.1f * z.z;
        z.w = z.w > 0.f ? z.w : 0.1f * z.w;

        red_add_v4(g_aggr + (size_t)d * HID + lane * 4, z);
    }
}

// ---------------------------------------------------------------------------
// Update: out = relu(cat[aggr, h_affine] @ W_up + b_up) + BN stats.
// (unchanged from R10 — validated at 328 us/layer)
// ---------------------------------------------------------------------------
#define UNTILE 64
#define UKP 132
#define UKP4 (UKP / 4)           // 33
#define KHALF 128
#define KHALF4 (KHALF / 4)       // 32
#define UPD_SMEM ((HID * UKP + UNTILE * KHALF) * 4)  // 100352

__global__ __launch_bounds__(256, 2) void update_kernel(
    int sel, const float* __restrict__ Wu, const float* __restrict__ bu)
{
    float* Ws = sm_dyn;                  // transposed [128 c][132 k-pad]
    float* ins = sm_dyn + HID * UKP;     // [64 r][128 k]
    __shared__ float s_sum[HID], s_sq[HID];

    const float* __restrict__ h_in = g_hbuf[sel];
    float* __restrict__ h_out = g_hbuf[sel ^ 1];

    const int tid = threadIdx.x;
    const int lane = tid & 31;
    const int wid = tid >> 5;
    const int n0 = blockIdx.x * UNTILE;

    if (tid < HID) { s_sum[tid] = 0.f; s_sq[tid] = 0.f; }

    const int r0 = wid * 8;
    unsigned long long acc[8][4];
#pragma unroll
    for (int r = 0; r < 8; r++)
#pragma unroll
        for (int j = 0; j < 4; j++) acc[r][j] = 0ULL;

    const ulonglong2* Wst2 = (const ulonglong2*)Ws;
    const ulonglong2* ins2 = (const ulonglong2*)(ins + r0 * KHALF);

#pragma unroll 1
    for (int p = 0; p < 2; p++) {
        {
            float4* Ws4 = (float4*)Ws;
            for (int i = tid; i < KHALF4 * HID; i += 256) {
                const int c = i & 127;
                const int k4 = i >> 7;
                float4 v;
                v.x = Wu[(p * KHALF + 4 * k4 + 0) * HID + c];
                v.y = Wu[(p * KHALF + 4 * k4 + 1) * HID + c];
                v.z = Wu[(p * KHALF + 4 * k4 + 2) * HID + c];
                v.w = Wu[(p * KHALF + 4 * k4 + 3) * HID + c];
                Ws4[c * UKP4 + k4] = v;
            }
        }
        {
            float4* ins4 = (float4*)ins;
            if (p == 0) {
                for (int i = tid; i < UNTILE * 32; i += 256) {
                    int r = i >> 5, q = i & 31;
                    ins4[i] = *(const float4*)(g_aggr + (size_t)(n0 + r) * HID + q * 4);
                }
            } else {
                for (int i = tid; i < UNTILE * 32; i += 256) {
                    int r = i >> 5, q = i & 31;
                    float4 v = *(const float4*)(h_in + (size_t)(n0 + r) * HID + q * 4);
                    float4 sc = ((const float4*)g_scale)[q];
                    float4 of = ((const float4*)g_shift)[q];
                    v.x = fmaf(v.x, sc.x, of.x);
                    v.y = fmaf(v.y, sc.y, of.y);
                    v.z = fmaf(v.z, sc.z, of.z);
                    v.w = fmaf(v.w, sc.w, of.w);
                    ins4[i] = v;
                }
            }
        }
        __syncthreads();

        for (int k4 = 0; k4 < KHALF4; k4++) {
            const ulonglong2 w0 = Wst2[(lane) * UKP4 + k4];
            const ulonglong2 w1 = Wst2[(lane + 32) * UKP4 + k4];
            const ulonglong2 w2 = Wst2[(lane + 64) * UKP4 + k4];
            const ulonglong2 w3 = Wst2[(lane + 96) * UKP4 + k4];
#pragma unroll
            for (int r = 0; r < 8; r++) {
                const ulonglong2 v = ins2[r * KHALF4 + k4];   // broadcast
                FMA2(acc[r][0], v.x, w0.x); FMA2(acc[r][0], v.y, w0.y);
                FMA2(acc[r][1], v.x, w1.x); FMA2(acc[r][1], v.y, w1.y);
                FMA2(acc[r][2], v.x, w2.x); FMA2(acc[r][2], v.y, w2.y);
                FMA2(acc[r][3], v.x, w3.x); FMA2(acc[r][3], v.y, w3.y);
            }
        }
        __syncthreads();
    }

    const float b0 = bu[lane], b1 = bu[lane + 32], b2 = bu[lane + 64], b3 = bu[lane + 96];
    float psum[4] = {0.f, 0.f, 0.f, 0.f};
    float psq[4] = {0.f, 0.f, 0.f, 0.f};
#pragma unroll
    for (int r = 0; r < 8; r++) {
        float* orow = h_out + (size_t)(n0 + r0 + r) * HID;
        float lo, hi;
        UNPACK2(lo, hi, acc[r][0]); float z0 = fmaxf(lo + hi + b0, 0.f);
        UNPACK2(lo, hi, acc[r][1]); float z1 = fmaxf(lo + hi + b1, 0.f);
        UNPACK2(lo, hi, acc[r][2]); float z2 = fmaxf(lo + hi + b2, 0.f);
        UNPACK2(lo, hi, acc[r][3]); float z3 = fmaxf(lo + hi + b3, 0.f);
        orow[lane] = z0; orow[lane + 32] = z1; orow[lane + 64] = z2; orow[lane + 96] = z3;
        psum[0] += z0; psum[1] += z1; psum[2] += z2; psum[3] += z3;
        psq[0] += z0 * z0; psq[1] += z1 * z1; psq[2] += z2 * z2; psq[3] += z3 * z3;
    }
    atomicAdd(&s_sum[lane], psum[0]);      atomicAdd(&s_sq[lane], psq[0]);
    atomicAdd(&s_sum[lane + 32], psum[1]); atomicAdd(&s_sq[lane + 32], psq[1]);
    atomicAdd(&s_sum[lane + 64], psum[2]); atomicAdd(&s_sq[lane + 64], psq[2]);
    atomicAdd(&s_sum[lane + 96], psum[3]); atomicAdd(&s_sq[lane + 96], psq[3]);
    __syncthreads();
    if (tid < HID) {
        atomicAdd(&g_bnsum[tid], s_sum[tid]);
        atomicAdd(&g_bnsq[tid], s_sq[tid]);
    }
}

// ---------------------------------------------------------------------------
// BN coefficients + zero aggr for next layer (streaming stores only)
// ---------------------------------------------------------------------------
__global__ void coef_zero_kernel(const float* __restrict__ gamma,
                                 const float* __restrict__ beta)
{
    size_t idx = (size_t)blockIdx.x * blockDim.x + threadIdx.x;
    size_t stride = (size_t)gridDim.x * blockDim.x;
    float4 z4 = {0.f, 0.f, 0.f, 0.f};
    float4* a4 = (float4*)g_aggr;
    for (size_t i = idx; i < (size_t)NNODES * HID / 4; i += stride) a4[i] = z4;
    if (blockIdx.x == 0 && threadIdx.x < HID) {
        int c = threadIdx.x;
        float mu = g_bnsum[c] * (1.f / NNODES);
        float var = g_bnsq[c] * (1.f / NNODES) - mu * mu;
        var = fmaxf(var, 0.f);
        float s = gamma[c] * rsqrtf(var + BN_EPS);
        g_scale[c] = s;
        g_shift[c] = beta[c] - mu * s;
        g_bnsum[c] = 0.f;
        g_bnsq[c] = 0.f;
    }
}

// ---------------------------------------------------------------------------
// Pooling: segmented (batch sorted); applies final BN affine
// ---------------------------------------------------------------------------
#define PNODES 32
__global__ __launch_bounds__(128) void pool_kernel(
    const int* __restrict__ batch, float* __restrict__ out)
{
    const float* __restrict__ h = g_hbuf[DEPTH & 1];
    const int n0 = blockIdx.x * PNODES;
    const int c = threadIdx.x;
    const float sc = g_scale[c];
    const float of = g_shift[c];

    int gprev = batch[n0];
    float acc = 0.f;
    int cnt = 0;
#pragma unroll 4
    for (int r = 0; r < PNODES; r++) {
        const int n = n0 + r;
        const int g = batch[n];
        const float v = fmaf(h[(size_t)n * HID + c], sc, of);
        if (g != gprev) {
            atomicAdd(&out[(size_t)gprev * HID + c], acc);
            if (c == 0) atomicAdd(&g_cnt[gprev], (float)cnt);
            acc = 0.f; cnt = 0; gprev = g;
        }
        acc += v; cnt++;
    }
    atomicAdd(&out[(size_t)gprev * HID + c], acc);
    if (c == 0) atomicAdd(&g_cnt[gprev], (float)cnt);
}

__global__ void pool_div_kernel(float* __restrict__ out)
{
    size_t i = (size_t)blockIdx.x * blockDim.x + threadIdx.x;
    if (i < (size_t)NGRAPHS * HID) {
        int g = (int)(i >> 7);
        out[i] /= fmaxf(g_cnt[g], 1.f);
    }
}

// ---------------------------------------------------------------------------
// Launch
// ---------------------------------------------------------------------------
extern "C" void kernel_launch(void* const* d_in, const int* in_sizes, int n_in,
                              void* d_out, int out_size)
{
    const float* x      = (const float*)d_in[0];
    const int*   eidx   = (const int*)d_in[1];     // [2, E]
    const float* eattr  = (const float*)d_in[2];
    const int*   batch  = (const int*)d_in[3];
    const float* W_in   = (const float*)d_in[4];
    const float* b_in   = (const float*)d_in[5];
    const float* W_msg  = (const float*)d_in[6];   // [4,139,128]
    const float* b_msg  = (const float*)d_in[7];   // [4,128]
    const float* W_up   = (const float*)d_in[8];   // [4,256,128]
    const float* b_up   = (const float*)d_in[9];   // [4,128]
    const float* gamma  = (const float*)d_in[10];
    const float* beta   = (const float*)d_in[11];
    float* out = (float*)d_out;

    const int* src = eidx;
    const int* dst = eidx + NEDGES;

    cudaFuncSetAttribute(msg_node_kernel, cudaFuncAttributeMaxDynamicSharedMemorySize, MSG_SMEM);
    cudaFuncSetAttribute(update_kernel, cudaFuncAttributeMaxDynamicSharedMemorySize, UPD_SMEM);

    init_kernel<<<2048, 256>>>(out);
    input_proj_kernel<<<NNODES / 8, 128>>>(x, W_in, b_in);

    for (int i = 0; i < DEPTH; i++) {
        msg_node_kernel<<<NNODES / 64, 256, MSG_SMEM>>>(
            i & 1, W_msg + (size_t)i * KMSG * HID);
        edge_scatter_kernel<<<NEDGES / EB, 256>>>(
            src, dst, eattr, W_msg + (size_t)i * KMSG * HID, b_msg + i * HID);
        update_kernel<<<NNODES / UNTILE, 256, UPD_SMEM>>>(
            i & 1, W_up + (size_t)i * KUP * HID, b_up + i * HID);
        coef_zero_kernel<<<2048, 256>>>(gamma + i * HID, beta + i * HID);
    }

    pool_kernel<<<NNODES / PNODES, 128>>>(batch, out);
    pool_div_kernel<<<(NGRAPHS * HID + 255) / 256, 256>>>(out);
}